// round 4
// baseline (speedup 1.0000x reference)
#include <cuda_runtime.h>
#include <cuda_bf16.h>
#include <cstdint>

#define RB    32
#define NTHR  256
#define KT1   14      // K=224 (192 h + 15 xn + 16 hmem + 1 pad)
#define KT2   24      // K=384 (192 h + 192 hs1)
#define GSTR  776

__device__ uint4 d_W1p[96 * KT1 * 32];
__device__ uint4 d_W2p[96 * KT2 * 32];
__device__ float d_hs1[4096 * 60 * 192];

struct Smem {
    uint4 fragH[KT2 * 2 * 32];   // A-fragments (bf16 hi), [kt][mt][lane] -> 4 regs
    uint4 fragL[KT2 * 2 * 32];   // A-fragments (bf16 residual)
    float g[RB * GSTR];          // gate pre-activations fp32
    float c[RB * 192];
    float h[RB * 192];
    float sn[RB * 24];
    float bias[768];
    float Wlat[16 * 193];
    float lat[RB * 17];
    float blat[16];
    float Wout[5 * 16];
    float bout[5];
    float Wsfco[5 * 193];
    float bsfco[5];
    float ysca[5];
};

__device__ __forceinline__ float fsig(float x) { return 1.0f / (1.0f + __expf(-x)); }
__device__ __forceinline__ float ftanh(float x) {
    float e = __expf(2.0f * x);
    return 1.0f - 2.0f / (e + 1.0f);
}

__device__ __forceinline__ uint32_t bfp(float x, float y) {
    __nv_bfloat162 t = __floats2bfloat162_rn(x, y);
    return *reinterpret_cast<uint32_t*>(&t);
}

__device__ __forceinline__ void split2(float x, float y, uint32_t& hi, uint32_t& lo) {
    __nv_bfloat16 bx = __float2bfloat16(x), by = __float2bfloat16(y);
    hi = ((uint32_t)__bfloat16_as_ushort(by) << 16) | (uint32_t)__bfloat16_as_ushort(bx);
    lo = bfp(x - __bfloat162float(bx), y - __bfloat162float(by));
}

// write one bf16x2 pair (cols 2p,2p+1 of row) into MMA A-fragment layout
__device__ __forceinline__ void put_frag(Smem& s, int row, int p, float v0, float v1) {
    int kt = p >> 3, qq = p & 7, mt = row >> 4, rr = row & 15;
    int off = ((((kt * 2 + mt) * 32) + ((rr & 7) * 4 + (qq & 3))) << 2)
            + ((qq >> 2) * 2 + (rr >> 3));
    uint32_t hi, lo;
    split2(v0, v1, hi, lo);
    reinterpret_cast<uint32_t*>(s.fragH)[off] = hi;
    reinterpret_cast<uint32_t*>(s.fragL)[off] = lo;
}

__device__ __forceinline__ void mma4(float* c, const uint32_t* a, uint32_t b0, uint32_t b1) {
    asm volatile(
        "mma.sync.aligned.m16n8k16.row.col.f32.bf16.bf16.f32 "
        "{%0,%1,%2,%3},{%4,%5,%6,%7},{%8,%9},{%0,%1,%2,%3};\n"
        : "+f"(c[0]), "+f"(c[1]), "+f"(c[2]), "+f"(c[3])
        : "r"(a[0]), "r"(a[1]), "r"(a[2]), "r"(a[3]), "r"(b0), "r"(b1));
}

// g[32][768] = A[32][16*KT] @ W^T  via bf16x3; warp w owns gate cols [96w, 96w+96)
template<int KT>
__device__ __forceinline__ void gemm(Smem& s, const uint4* __restrict__ Wp, int warp, int lane) {
    float acc[2][12][4];
#pragma unroll
    for (int m = 0; m < 2; m++)
#pragma unroll
        for (int n = 0; n < 12; n++)
#pragma unroll
            for (int q = 0; q < 4; q++) acc[m][n][q] = 0.0f;

    const uint4* wb = Wp + (warp * 12 * KT) * 32 + lane;
    for (int kt = 0; kt < KT; kt++) {
        uint4 ah0 = s.fragH[(kt * 2 + 0) * 32 + lane];
        uint4 ah1 = s.fragH[(kt * 2 + 1) * 32 + lane];
        uint4 al0 = s.fragL[(kt * 2 + 0) * 32 + lane];
        uint4 al1 = s.fragL[(kt * 2 + 1) * 32 + lane];
#pragma unroll
        for (int nt = 0; nt < 12; nt++) {
            uint4 w = wb[(nt * KT + kt) * 32];   // {hi_b0, hi_b1, lo_b0, lo_b1}
            mma4(acc[0][nt], (const uint32_t*)&ah0, w.x, w.y);
            mma4(acc[1][nt], (const uint32_t*)&ah1, w.x, w.y);
            mma4(acc[0][nt], (const uint32_t*)&ah0, w.z, w.w);
            mma4(acc[1][nt], (const uint32_t*)&ah1, w.z, w.w);
            mma4(acc[0][nt], (const uint32_t*)&al0, w.x, w.y);
            mma4(acc[1][nt], (const uint32_t*)&al1, w.x, w.y);
        }
    }
    int r0 = lane >> 2, c0 = (lane & 3) * 2, nb = warp * 96;
#pragma unroll
    for (int m = 0; m < 2; m++)
#pragma unroll
        for (int nt = 0; nt < 12; nt++) {
            int row = m * 16 + r0, col = nb + nt * 8 + c0;
            *(float2*)&s.g[row * GSTR + col]       = make_float2(acc[m][nt][0], acc[m][nt][1]);
            *(float2*)&s.g[(row + 8) * GSTR + col] = make_float2(acc[m][nt][2], acc[m][nt][3]);
        }
}

// pre-swizzle weights into B-fragment order, bf16 hi + residual lo
__global__ void pack_kernel(const float* __restrict__ Wih1, const float* __restrict__ Whh1,
                            const float* __restrict__ Wih2, const float* __restrict__ Whh2) {
    int tid = blockIdx.x * blockDim.x + threadIdx.x;
    const int N2 = 96 * KT2 * 32, N1 = 96 * KT1 * 32;
    if (tid < N2) {
        int lane = tid & 31, t = tid >> 5, kt = t % KT2, nt = t / KT2;
        int n = nt * 8 + (lane >> 2), k0 = kt * 16 + (lane & 3) * 2;
        int ks[4] = {k0, k0 + 1, k0 + 8, k0 + 9};
        float w[4];
#pragma unroll
        for (int i = 0; i < 4; i++) {
            int k = ks[i];
            w[i] = (k < 192) ? Whh2[n * 192 + k] : Wih2[n * 192 + (k - 192)];
        }
        uint4 u; uint32_t hx, lx, hy, ly;
        split2(w[0], w[1], hx, lx); split2(w[2], w[3], hy, ly);
        u.x = hx; u.y = hy; u.z = lx; u.w = ly;
        d_W2p[tid] = u;
    } else if (tid < N2 + N1) {
        int t0 = tid - N2;
        int lane = t0 & 31, t = t0 >> 5, kt = t % KT1, nt = t / KT1;
        int n = nt * 8 + (lane >> 2), k0 = kt * 16 + (lane & 3) * 2;
        int ks[4] = {k0, k0 + 1, k0 + 8, k0 + 9};
        float w[4];
#pragma unroll
        for (int i = 0; i < 4; i++) {
            int k = ks[i];
            if (k < 192)      w[i] = Whh1[n * 192 + k];
            else if (k < 223) w[i] = Wih1[n * 31 + (k - 192)];
            else              w[i] = 0.0f;
        }
        uint4 u; uint32_t hx, lx, hy, ly;
        split2(w[0], w[1], hx, lx); split2(w[2], w[3], hy, ly);
        u.x = hx; u.y = hy; u.z = lx; u.w = ly;
        d_W1p[t0] = u;
    }
}

__global__ void __launch_bounds__(NTHR, 1) lstm_main(
    const float* __restrict__ x_lev, const float* __restrict__ x_sfc,
    const float* __restrict__ h_mem,
    const float* __restrict__ xmean_lev, const float* __restrict__ xdiv_lev,
    const float* __restrict__ xmean_sca, const float* __restrict__ xdiv_sca,
    const float* __restrict__ yscale_lev, const float* __restrict__ yscale_sca,
    const float* __restrict__ b1, const float* __restrict__ b2,
    const float* __restrict__ Wsfc1, const float* __restrict__ bsfc1,
    const float* __restrict__ Wsfc2, const float* __restrict__ bsfc2,
    const float* __restrict__ Wtoa1, const float* __restrict__ btoa1,
    const float* __restrict__ Wtoa2, const float* __restrict__ btoa2,
    const float* __restrict__ Wlat, const float* __restrict__ blat,
    const float* __restrict__ Wout, const float* __restrict__ bout,
    const float* __restrict__ Wsfcout, const float* __restrict__ bsfcout,
    float* __restrict__ out)
{
    extern __shared__ char smraw[];
    Smem& s = *reinterpret_cast<Smem*>(smraw);
    const int tid = threadIdx.x, warp = tid >> 5, lane = tid & 31;
    const int bbase = blockIdx.x * RB;
    float* out_lev = out;                    // [4096,60,5]
    float* out_sfc = out + 4096 * 60 * 5;    // [4096,5]
    float* out_lat = out_sfc + 4096 * 5;     // [4096,60,16]

    // ---- constants -> smem ----
    for (int i = tid; i < RB * 24; i += NTHR) {
        int r = i / 24, k = i % 24;
        s.sn[i] = (x_sfc[(bbase + r) * 24 + k] - xmean_sca[k]) / xdiv_sca[k];
    }
    for (int i = tid; i < 768; i += NTHR) s.bias[i] = b1[i];
    for (int i = tid; i < 16 * 192; i += NTHR) { int j = i / 192, k = i % 192; s.Wlat[j * 193 + k] = Wlat[i]; }
    for (int i = tid; i < 16; i += NTHR) s.blat[i] = blat[i];
    for (int i = tid; i < 80; i += NTHR) s.Wout[i] = Wout[i];
    for (int i = tid; i < 5; i += NTHR) { s.bout[i] = bout[i]; s.bsfco[i] = bsfcout[i]; s.ysca[i] = yscale_sca[i]; }
    for (int i = tid; i < 5 * 192; i += NTHR) { int n = i / 192, k = i % 192; s.Wsfco[n * 193 + k] = Wsfcout[i]; }
    __syncthreads();

    // ---- h0 = tanh(sn@Wsfc1^T+b), c0 = tanh(sn@Wsfc2^T+b) ----
    for (int it = 0; it < 24; it++) {
        int idx = it * NTHR + tid, r = idx / 192, k = idx % 192;
        float s1 = bsfc1[k], s2 = bsfc2[k];
#pragma unroll 4
        for (int t = 0; t < 24; t++) {
            float v = s.sn[r * 24 + t];
            s1 += v * Wsfc1[k * 24 + t];
            s2 += v * Wsfc2[k * 24 + t];
        }
        s.h[r * 192 + k] = ftanh(s1);
        s.c[r * 192 + k] = ftanh(s2);
    }
    __syncthreads();
    // h0 fragments + x fragments for level 59
    for (int it = 0; it < 12; it++) {
        int idx = it * NTHR + tid, r = idx / 96, cp = idx % 96;
        put_frag(s, r, cp, s.h[r * 192 + 2 * cp], s.h[r * 192 + 2 * cp + 1]);
    }
    {
        const int ln = 59;
        for (int it = 0; it < 2; it++) {
            int idx = it * NTHR + tid, r = idx >> 4, q = idx & 15;
            float v[2];
#pragma unroll
            for (int u = 0; u < 2; u++) {
                int j = q * 2 + u;
                int base = (bbase + r) * 60 + ln;
                float val;
                if (j < 15)      val = (x_lev[base * 15 + j] - xmean_lev[ln * 15 + j]) / xdiv_lev[ln * 15 + j];
                else if (j < 31) val = h_mem[base * 16 + (j - 15)];
                else             val = 0.0f;
                v[u] = val;
            }
            put_frag(s, r, 96 + q, v[0], v[1]);
        }
    }
    __syncthreads();

    // ---- layer 1: levels 59..0 ----
    for (int l = 59; l >= 0; l--) {
        gemm<KT1>(s, d_W1p, warp, lane);
        __syncthreads();
        for (int it = 0; it < 12; it++) {
            int idx = it * NTHR + tid, r = idx / 96, cp = idx % 96, col = 2 * cp;
            float2 gi = *(float2*)&s.g[r * GSTR + col];
            float2 gf = *(float2*)&s.g[r * GSTR + col + 192];
            float2 gg = *(float2*)&s.g[r * GSTR + col + 384];
            float2 go = *(float2*)&s.g[r * GSTR + col + 576];
            gi.x += s.bias[col];       gi.y += s.bias[col + 1];
            gf.x += s.bias[col + 192]; gf.y += s.bias[col + 193];
            gg.x += s.bias[col + 384]; gg.y += s.bias[col + 385];
            go.x += s.bias[col + 576]; go.y += s.bias[col + 577];
            float c0 = s.c[r * 192 + col], c1 = s.c[r * 192 + col + 1];
            float cn0 = fsig(gf.x) * c0 + fsig(gi.x) * ftanh(gg.x);
            float cn1 = fsig(gf.y) * c1 + fsig(gi.y) * ftanh(gg.y);
            float h0 = fsig(go.x) * ftanh(cn0);
            float h1 = fsig(go.y) * ftanh(cn1);
            s.c[r * 192 + col] = cn0; s.c[r * 192 + col + 1] = cn1;
            put_frag(s, r, cp, h0, h1);
            int base = (bbase + r) * 60 + l;
            *(float2*)&d_hs1[base * 192 + col] = make_float2(h0, h1);
        }
        if (l > 0) {
            const int ln = l - 1;
            for (int it = 0; it < 2; it++) {
                int idx = it * NTHR + tid, r = idx >> 4, q = idx & 15;
                float v[2];
#pragma unroll
                for (int u = 0; u < 2; u++) {
                    int j = q * 2 + u;
                    int base = (bbase + r) * 60 + ln;
                    float val;
                    if (j < 15)      val = (x_lev[base * 15 + j] - xmean_lev[ln * 15 + j]) / xdiv_lev[ln * 15 + j];
                    else if (j < 31) val = h_mem[base * 16 + (j - 15)];
                    else             val = 0.0f;
                    v[u] = val;
                }
                put_frag(s, r, 96 + q, v[0], v[1]);
            }
        }
        __syncthreads();
    }

    // ---- transition to layer 2 ----
    for (int i = tid; i < 768; i += NTHR) s.bias[i] = b2[i];
    for (int it = 0; it < 24; it++) {
        int idx = it * NTHR + tid, r = idx / 192, k = idx % 192;
        float t0 = s.sn[r * 24 + 0], t1 = s.sn[r * 24 + 1];
        s.h[r * 192 + k] = ftanh(btoa1[k] + t0 * Wtoa1[k * 2] + t1 * Wtoa1[k * 2 + 1]);
        s.c[r * 192 + k] = ftanh(btoa2[k] + t0 * Wtoa2[k * 2] + t1 * Wtoa2[k * 2 + 1]);
    }
    __syncthreads();
    for (int it = 0; it < 12; it++) {
        int idx = it * NTHR + tid, r = idx / 96, cp = idx % 96;
        put_frag(s, r, cp, s.h[r * 192 + 2 * cp], s.h[r * 192 + 2 * cp + 1]);
    }
    for (int it = 0; it < 12; it++) {
        int idx = it * NTHR + tid, r = idx / 96, q = idx % 96;
        int base = (bbase + r) * 60 + 0;
        float2 v = *(float2*)&d_hs1[base * 192 + 2 * q];
        put_frag(s, r, 96 + q, v.x, v.y);
    }
    __syncthreads();

    // ---- layer 2: levels 0..59 ----
    for (int l = 0; l < 60; l++) {
        gemm<KT2>(s, d_W2p, warp, lane);
        __syncthreads();
        for (int it = 0; it < 12; it++) {
            int idx = it * NTHR + tid, r = idx / 96, cp = idx % 96, col = 2 * cp;
            float2 gi = *(float2*)&s.g[r * GSTR + col];
            float2 gf = *(float2*)&s.g[r * GSTR + col + 192];
            float2 gg = *(float2*)&s.g[r * GSTR + col + 384];
            float2 go = *(float2*)&s.g[r * GSTR + col + 576];
            gi.x += s.bias[col];       gi.y += s.bias[col + 1];
            gf.x += s.bias[col + 192]; gf.y += s.bias[col + 193];
            gg.x += s.bias[col + 384]; gg.y += s.bias[col + 385];
            go.x += s.bias[col + 576]; go.y += s.bias[col + 577];
            float c0 = s.c[r * 192 + col], c1 = s.c[r * 192 + col + 1];
            float cn0 = fsig(gf.x) * c0 + fsig(gi.x) * ftanh(gg.x);
            float cn1 = fsig(gf.y) * c1 + fsig(gi.y) * ftanh(gg.y);
            float h0 = fsig(go.x) * ftanh(cn0);
            float h1 = fsig(go.y) * ftanh(cn1);
            s.c[r * 192 + col] = cn0; s.c[r * 192 + col + 1] = cn1;
            s.h[r * 192 + col] = h0;  s.h[r * 192 + col + 1] = h1;
            put_frag(s, r, cp, h0, h1);
        }
        if (l < 59) {
            for (int it = 0; it < 12; it++) {
                int idx = it * NTHR + tid, r = idx / 96, q = idx % 96;
                int base = (bbase + r) * 60 + (l + 1);
                float2 v = *(float2*)&d_hs1[base * 192 + 2 * q];
                put_frag(s, r, 96 + q, v.x, v.y);
            }
        }
        __syncthreads();
        // lat = h @ Wlat^T + blat
        for (int it = 0; it < 2; it++) {
            int idx = it * NTHR + tid, r = idx >> 4, j = idx & 15;
            float sum = s.blat[j];
#pragma unroll 8
            for (int k = 0; k < 192; k++) sum += s.h[r * 192 + k] * s.Wlat[j * 193 + k];
            s.lat[r * 17 + j] = sum;
            out_lat[((bbase + r) * 60 + l) * 16 + j] = sum;
        }
        __syncthreads();
        // out = (lat @ Wout^T + bout) / yscale_lev[l]
        if (tid < 160) {
            int r = tid / 5, n = tid % 5;
            float sum = s.bout[n];
#pragma unroll
            for (int j = 0; j < 16; j++) sum += s.lat[r * 17 + j] * s.Wout[n * 16 + j];
            out_lev[((bbase + r) * 60 + l) * 5 + n] = sum / yscale_lev[l * 5 + n];
        }
        // no barrier needed: next gemm touches only fragH/L (stable) and g (not read here)
    }
    __syncthreads();
    // out_sfc = (h_last @ Wsfcout^T + bsfcout) / yscale_sca
    if (tid < 160) {
        int r = tid / 5, n = tid % 5;
        float sum = s.bsfco[n];
#pragma unroll 8
        for (int k = 0; k < 192; k++) sum += s.h[r * 192 + k] * s.Wsfco[n * 193 + k];
        out_sfc[(bbase + r) * 5 + n] = sum / s.ysca[n];
    }
}

extern "C" void kernel_launch(void* const* d_in, const int* in_sizes, int n_in,
                              void* d_out, int out_size) {
    (void)in_sizes; (void)n_in; (void)out_size;
    const float* x_lev     = (const float*)d_in[0];
    const float* x_sfc     = (const float*)d_in[1];
    const float* h_mem     = (const float*)d_in[2];
    const float* xmean_lev = (const float*)d_in[3];
    const float* xdiv_lev  = (const float*)d_in[4];
    const float* xmean_sca = (const float*)d_in[5];
    const float* xdiv_sca  = (const float*)d_in[6];
    const float* yscale_lev = (const float*)d_in[7];
    const float* yscale_sca = (const float*)d_in[8];
    const float* Wih1 = (const float*)d_in[9];
    const float* Whh1 = (const float*)d_in[10];
    const float* b1   = (const float*)d_in[11];
    const float* Wih2 = (const float*)d_in[12];
    const float* Whh2 = (const float*)d_in[13];
    const float* b2   = (const float*)d_in[14];
    const float* Wsfc1 = (const float*)d_in[15];
    const float* bsfc1 = (const float*)d_in[16];
    const float* Wsfc2 = (const float*)d_in[17];
    const float* bsfc2 = (const float*)d_in[18];
    const float* Wtoa1 = (const float*)d_in[19];
    const float* btoa1 = (const float*)d_in[20];
    const float* Wtoa2 = (const float*)d_in[21];
    const float* btoa2 = (const float*)d_in[22];
    const float* Wlat  = (const float*)d_in[23];
    const float* blat  = (const float*)d_in[24];
    const float* Wout  = (const float*)d_in[25];
    const float* bout  = (const float*)d_in[26];
    const float* Wsfcout = (const float*)d_in[27];
    const float* bsfcout = (const float*)d_in[28];

    cudaFuncSetAttribute(lstm_main, cudaFuncAttributeMaxDynamicSharedMemorySize,
                         (int)sizeof(Smem));

    int npack = 96 * KT2 * 32 + 96 * KT1 * 32;
    pack_kernel<<<(npack + 255) / 256, 256>>>(Wih1, Whh1, Wih2, Whh2);

    lstm_main<<<128, NTHR, sizeof(Smem)>>>(
        x_lev, x_sfc, h_mem, xmean_lev, xdiv_lev, xmean_sca, xdiv_sca,
        yscale_lev, yscale_sca, b1, b2,
        Wsfc1, bsfc1, Wsfc2, bsfc2, Wtoa1, btoa1, Wtoa2, btoa2,
        Wlat, blat, Wout, bout, Wsfcout, bsfcout,
        (float*)d_out);
}

// round 5
// speedup vs baseline: 2.4979x; 2.4979x over previous
#include <cuda_runtime.h>
#include <cuda_fp16.h>
#include <cstdint>

#define RB    32
#define NTHR  256
#define KT1   14      // K=224 (192 h + 15 xn + 16 hmem + 1 pad)
#define KT2   24      // K=384 (192 h + 192 hs1)

__device__ uint2 d_W1p[96 * KT1 * 32];          // fp16 B-fragments, gate-permuted
__device__ uint2 d_W2p[96 * KT2 * 32];
__device__ uint4 d_hs1f[128 * 60 * 768];        // hs1 in fp16 A-fragment format

struct Smem {
    uint4 frag[KT2 * 2 * 32];    // fp16 A-fragments [kt][mt][lane] -> 4 words
    float h[RB * 192];
    float c[RB * 192];
    float sn[RB * 24];
    float Wlat[16 * 193];
    float lat[RB * 17];
    float blat[16];
    float Wout[5 * 16];
    float bout[5];
    float Wsfco[5 * 193];
    float bsfco[5];
    float ysca[5];
};

__device__ __forceinline__ float tanhf_fast(float x) {
    float y; asm("tanh.approx.f32 %0, %1;" : "=f"(y) : "f"(x)); return y;
}
__device__ __forceinline__ float sigf(float x) {
    return fmaf(tanhf_fast(0.5f * x), 0.5f, 0.5f);
}
__device__ __forceinline__ uint32_t h2pack(float x, float y) {
    __half2 h = __floats2half2_rn(x, y);
    return *reinterpret_cast<uint32_t*>(&h);
}

// write one fp16x2 pair (cols 2p,2p+1 of row) into MMA A-fragment layout
__device__ __forceinline__ void put_frag(uint32_t* fw, int row, int p, float v0, float v1) {
    int kt = p >> 3, qq = p & 7, mt = row >> 4, rr = row & 15;
    int cell = (kt * 2 + mt) * 32 + (rr & 7) * 4 + (qq & 3);
    int reg  = (qq >> 2) * 2 + (rr >> 3);
    fw[cell * 4 + reg] = h2pack(v0, v1);
}

__device__ __forceinline__ void mma4(float* c, const uint32_t* a, uint32_t b0, uint32_t b1) {
    asm volatile(
        "mma.sync.aligned.m16n8k16.row.col.f32.f16.f16.f32 "
        "{%0,%1,%2,%3},{%4,%5,%6,%7},{%8,%9},{%0,%1,%2,%3};\n"
        : "+f"(c[0]), "+f"(c[1]), "+f"(c[2]), "+f"(c[3])
        : "r"(a[0]), "r"(a[1]), "r"(a[2]), "r"(a[3]), "r"(b0), "r"(b1));
}

// g[32][96w..96w+96) = A[32][16*KT] @ W^T, accumulators init'd to bias
template<int KT>
__device__ __forceinline__ void gemm(const Smem& s, const uint2* __restrict__ Wp,
                                     int warp, int lane, const float bias[4][3][2],
                                     float acc[2][12][4]) {
#pragma unroll
    for (int m = 0; m < 2; m++)
#pragma unroll
        for (int g = 0; g < 4; g++)
#pragma unroll
            for (int j = 0; j < 3; j++)
#pragma unroll
                for (int q = 0; q < 2; q++)
#pragma unroll
                    for (int e = 0; e < 2; e++)
                        acc[m][g * 3 + j][2 * q + e] = bias[g][j][e];

    const uint2* wb = Wp + (warp * 12 * KT) * 32 + lane;
#pragma unroll 2
    for (int kt = 0; kt < KT; kt++) {
        uint2 wv[12];
#pragma unroll
        for (int nt = 0; nt < 12; nt++) wv[nt] = wb[(nt * KT + kt) * 32];
        uint4 f0 = s.frag[(kt * 2 + 0) * 32 + lane];
        uint4 f1 = s.frag[(kt * 2 + 1) * 32 + lane];
#pragma unroll
        for (int nt = 0; nt < 12; nt++) {
            mma4(acc[0][nt], (const uint32_t*)&f0, wv[nt].x, wv[nt].y);
            mma4(acc[1][nt], (const uint32_t*)&f1, wv[nt].x, wv[nt].y);
        }
    }
}

// pack weights into fp16 B-fragment order with gate-permuted columns:
// warp-local col c = gate*24 + unit  ->  orig row n = gate*192 + w*24 + unit
__global__ void pack_kernel(const float* __restrict__ Wih1, const float* __restrict__ Whh1,
                            const float* __restrict__ Wih2, const float* __restrict__ Whh2) {
    int tid = blockIdx.x * blockDim.x + threadIdx.x;
    const int N2 = 96 * KT2 * 32, N1 = 96 * KT1 * 32;
    if (tid < N2) {
        int lane = tid & 31, t = tid >> 5, kt = t % KT2, ntg = t / KT2;
        int w = ntg / 12, ntl = ntg % 12;
        int c = ntl * 8 + (lane >> 2);
        int n = (c / 24) * 192 + w * 24 + (c % 24);
        int k0 = kt * 16 + (lane & 3) * 2;
        int ks[4] = {k0, k0 + 1, k0 + 8, k0 + 9};
        float v[4];
#pragma unroll
        for (int i = 0; i < 4; i++) {
            int k = ks[i];
            v[i] = (k < 192) ? Whh2[n * 192 + k] : Wih2[n * 192 + (k - 192)];
        }
        uint2 u; u.x = h2pack(v[0], v[1]); u.y = h2pack(v[2], v[3]);
        d_W2p[tid] = u;
    } else if (tid < N2 + N1) {
        int t0 = tid - N2;
        int lane = t0 & 31, t = t0 >> 5, kt = t % KT1, ntg = t / KT1;
        int w = ntg / 12, ntl = ntg % 12;
        int c = ntl * 8 + (lane >> 2);
        int n = (c / 24) * 192 + w * 24 + (c % 24);
        int k0 = kt * 16 + (lane & 3) * 2;
        int ks[4] = {k0, k0 + 1, k0 + 8, k0 + 9};
        float v[4];
#pragma unroll
        for (int i = 0; i < 4; i++) {
            int k = ks[i];
            if (k < 192)      v[i] = Whh1[n * 192 + k];
            else if (k < 223) v[i] = Wih1[n * 31 + (k - 192)];
            else              v[i] = 0.0f;
        }
        uint2 u; u.x = h2pack(v[0], v[1]); u.y = h2pack(v[2], v[3]);
        d_W1p[t0] = u;
    }
}

__global__ void __launch_bounds__(NTHR, 1) lstm_main(
    const float* __restrict__ x_lev, const float* __restrict__ x_sfc,
    const float* __restrict__ h_mem,
    const float* __restrict__ xmean_lev, const float* __restrict__ xdiv_lev,
    const float* __restrict__ xmean_sca, const float* __restrict__ xdiv_sca,
    const float* __restrict__ yscale_lev, const float* __restrict__ yscale_sca,
    const float* __restrict__ b1, const float* __restrict__ b2,
    const float* __restrict__ Wsfc1, const float* __restrict__ bsfc1,
    const float* __restrict__ Wsfc2, const float* __restrict__ bsfc2,
    const float* __restrict__ Wtoa1, const float* __restrict__ btoa1,
    const float* __restrict__ Wtoa2, const float* __restrict__ btoa2,
    const float* __restrict__ Wlat, const float* __restrict__ blat,
    const float* __restrict__ Wout, const float* __restrict__ bout,
    const float* __restrict__ Wsfcout, const float* __restrict__ bsfcout,
    float* __restrict__ out)
{
    extern __shared__ char smraw[];
    Smem& s = *reinterpret_cast<Smem*>(smraw);
    uint32_t* fw = reinterpret_cast<uint32_t*>(s.frag);
    uint32_t* hs1w = reinterpret_cast<uint32_t*>(d_hs1f);
    const int tid = threadIdx.x, warp = tid >> 5, lane = tid & 31;
    const int l2i = lane & 3, l4 = lane >> 2;
    const int bbase = blockIdx.x * RB;
    float* out_lev = out;                     // [4096,60,5]
    float* out_sfc = out + 4096 * 60 * 5;     // [4096,5]
    float* out_lat = out_sfc + 4096 * 5;      // [4096,60,16]

    // ---- constants -> smem ----
    for (int i = tid; i < RB * 24; i += NTHR) {
        int r = i / 24, k = i % 24;
        s.sn[i] = (x_sfc[(bbase + r) * 24 + k] - xmean_sca[k]) / xdiv_sca[k];
    }
    for (int i = tid; i < 16 * 192; i += NTHR) { int j = i / 192, k = i % 192; s.Wlat[j * 193 + k] = Wlat[i]; }
    for (int i = tid; i < 16; i += NTHR) s.blat[i] = blat[i];
    for (int i = tid; i < 80; i += NTHR) s.Wout[i] = Wout[i];
    for (int i = tid; i < 5; i += NTHR) { s.bout[i] = bout[i]; s.bsfco[i] = bsfcout[i]; s.ysca[i] = yscale_sca[i]; }
    for (int i = tid; i < 5 * 192; i += NTHR) { int n = i / 192, k = i % 192; s.Wsfco[n * 193 + k] = Wsfcout[i]; }
    __syncthreads();

    // ---- h0 = tanh(sn@Wsfc1^T+b), c0 = tanh(sn@Wsfc2^T+b) ----
    for (int it = 0; it < 24; it++) {
        int idx = it * NTHR + tid, r = idx / 192, k = idx % 192;
        float s1 = bsfc1[k], s2 = bsfc2[k];
#pragma unroll 4
        for (int t = 0; t < 24; t++) {
            float v = s.sn[r * 24 + t];
            s1 += v * Wsfc1[k * 24 + t];
            s2 += v * Wsfc2[k * 24 + t];
        }
        s.h[r * 192 + k] = tanhf_fast(s1);
        s.c[r * 192 + k] = tanhf_fast(s2);
    }
    __syncthreads();

    // per-lane persistent state: bias + cell state in registers
    float bias[4][3][2];
#pragma unroll
    for (int g = 0; g < 4; g++)
#pragma unroll
        for (int j = 0; j < 3; j++)
#pragma unroll
            for (int e = 0; e < 2; e++)
                bias[g][j][e] = b1[g * 192 + warp * 24 + 8 * j + 2 * l2i + e];
    float creg[2][3][2][2];
#pragma unroll
    for (int m = 0; m < 2; m++)
#pragma unroll
        for (int j = 0; j < 3; j++)
#pragma unroll
            for (int q = 0; q < 2; q++)
#pragma unroll
                for (int e = 0; e < 2; e++)
                    creg[m][j][q][e] = s.c[(m * 16 + l4 + 8 * q) * 192 + warp * 24 + 8 * j + 2 * l2i + e];

    // h0 fragments + x fragments for level 59
    for (int it = 0; it < 12; it++) {
        int idx = it * NTHR + tid, r = idx / 96, cp = idx % 96;
        put_frag(fw, r, cp, s.h[r * 192 + 2 * cp], s.h[r * 192 + 2 * cp + 1]);
    }
    {
        const int ln = 59;
        for (int it = 0; it < 2; it++) {
            int idx = it * NTHR + tid, r = idx >> 4, p = idx & 15;
            float v[2];
#pragma unroll
            for (int u = 0; u < 2; u++) {
                int j = p * 2 + u;
                int base = (bbase + r) * 60 + ln;
                float val;
                if (j < 15)      val = (x_lev[base * 15 + j] - xmean_lev[ln * 15 + j]) / xdiv_lev[ln * 15 + j];
                else if (j < 31) val = h_mem[base * 16 + (j - 15)];
                else             val = 0.0f;
                v[u] = val;
            }
            put_frag(fw, r, 96 + p, v[0], v[1]);
        }
    }
    __syncthreads();

    // ---- layer 1: levels 59..0 ----
    for (int l = 59; l >= 0; l--) {
        float acc[2][12][4];
        gemm<KT1>(s, d_W1p, warp, lane, bias, acc);
        __syncthreads();
#pragma unroll
        for (int m = 0; m < 2; m++)
#pragma unroll
            for (int j = 0; j < 3; j++) {
                int kt = (3 * warp + j) >> 1;
                int reghalf = ((3 * warp + j) & 1) * 2;
#pragma unroll
                for (int q = 0; q < 2; q++) {
                    float gi0 = acc[m][j][2*q],   gi1 = acc[m][j][2*q+1];
                    float gf0 = acc[m][3+j][2*q], gf1 = acc[m][3+j][2*q+1];
                    float gg0 = acc[m][6+j][2*q], gg1 = acc[m][6+j][2*q+1];
                    float go0 = acc[m][9+j][2*q], go1 = acc[m][9+j][2*q+1];
                    float c0 = sigf(gf0) * creg[m][j][q][0] + sigf(gi0) * tanhf_fast(gg0);
                    float c1 = sigf(gf1) * creg[m][j][q][1] + sigf(gi1) * tanhf_fast(gg1);
                    creg[m][j][q][0] = c0; creg[m][j][q][1] = c1;
                    float h0 = sigf(go0) * tanhf_fast(c0);
                    float h1 = sigf(go1) * tanhf_fast(c1);
                    uint32_t word = h2pack(h0, h1);
                    fw[(((kt * 2 + m) * 32 + lane) << 2) + reghalf + q] = word;
                    hs1w[(((blockIdx.x * 60 + l) * 24 + kt * 2 + m) << 7) + (lane << 2) + reghalf + q] = word;
                }
            }
        if (l > 0) {
            const int ln = l - 1;
            for (int it = 0; it < 2; it++) {
                int idx = it * NTHR + tid, r = idx >> 4, p = idx & 15;
                float v[2];
#pragma unroll
                for (int u = 0; u < 2; u++) {
                    int j = p * 2 + u;
                    int base = (bbase + r) * 60 + ln;
                    float val;
                    if (j < 15)      val = (x_lev[base * 15 + j] - xmean_lev[ln * 15 + j]) / xdiv_lev[ln * 15 + j];
                    else if (j < 31) val = h_mem[base * 16 + (j - 15)];
                    else             val = 0.0f;
                    v[u] = val;
                }
                put_frag(fw, r, 96 + p, v[0], v[1]);
            }
        }
        __syncthreads();
    }

    // ---- transition to layer 2 ----
#pragma unroll
    for (int g = 0; g < 4; g++)
#pragma unroll
        for (int j = 0; j < 3; j++)
#pragma unroll
            for (int e = 0; e < 2; e++)
                bias[g][j][e] = b2[g * 192 + warp * 24 + 8 * j + 2 * l2i + e];
    for (int it = 0; it < 24; it++) {
        int idx = it * NTHR + tid, r = idx / 192, k = idx % 192;
        float t0 = s.sn[r * 24 + 0], t1 = s.sn[r * 24 + 1];
        s.h[r * 192 + k] = tanhf_fast(btoa1[k] + t0 * Wtoa1[k * 2] + t1 * Wtoa1[k * 2 + 1]);
        s.c[r * 192 + k] = tanhf_fast(btoa2[k] + t0 * Wtoa2[k * 2] + t1 * Wtoa2[k * 2 + 1]);
    }
    __syncthreads();
#pragma unroll
    for (int m = 0; m < 2; m++)
#pragma unroll
        for (int j = 0; j < 3; j++)
#pragma unroll
            for (int q = 0; q < 2; q++)
#pragma unroll
                for (int e = 0; e < 2; e++)
                    creg[m][j][q][e] = s.c[(m * 16 + l4 + 8 * q) * 192 + warp * 24 + 8 * j + 2 * l2i + e];
    for (int it = 0; it < 12; it++) {
        int idx = it * NTHR + tid, r = idx / 96, cp = idx % 96;
        put_frag(fw, r, cp, s.h[r * 192 + 2 * cp], s.h[r * 192 + 2 * cp + 1]);
    }
    {   // hs1 frags for level 0: coalesced copy straight into kt 12..23
        const uint4* src = d_hs1f + (size_t)(blockIdx.x * 60 + 0) * 768;
#pragma unroll
        for (int i = 0; i < 3; i++) s.frag[768 + i * NTHR + tid] = src[i * NTHR + tid];
    }
    __syncthreads();

    // ---- layer 2: levels 0..59 ----
    for (int l = 0; l < 60; l++) {
        float acc[2][12][4];
        gemm<KT2>(s, d_W2p, warp, lane, bias, acc);
        __syncthreads();
#pragma unroll
        for (int m = 0; m < 2; m++)
#pragma unroll
            for (int j = 0; j < 3; j++) {
                int kt = (3 * warp + j) >> 1;
                int reghalf = ((3 * warp + j) & 1) * 2;
                int col = warp * 24 + 8 * j + 2 * l2i;
#pragma unroll
                for (int q = 0; q < 2; q++) {
                    float gi0 = acc[m][j][2*q],   gi1 = acc[m][j][2*q+1];
                    float gf0 = acc[m][3+j][2*q], gf1 = acc[m][3+j][2*q+1];
                    float gg0 = acc[m][6+j][2*q], gg1 = acc[m][6+j][2*q+1];
                    float go0 = acc[m][9+j][2*q], go1 = acc[m][9+j][2*q+1];
                    float c0 = sigf(gf0) * creg[m][j][q][0] + sigf(gi0) * tanhf_fast(gg0);
                    float c1 = sigf(gf1) * creg[m][j][q][1] + sigf(gi1) * tanhf_fast(gg1);
                    creg[m][j][q][0] = c0; creg[m][j][q][1] = c1;
                    float h0 = sigf(go0) * tanhf_fast(c0);
                    float h1 = sigf(go1) * tanhf_fast(c1);
                    fw[(((kt * 2 + m) * 32 + lane) << 2) + reghalf + q] = h2pack(h0, h1);
                    int row = m * 16 + l4 + 8 * q;
                    *(float2*)&s.h[row * 192 + col] = make_float2(h0, h1);
                }
            }
        if (l < 59) {
            const uint4* src = d_hs1f + (size_t)(blockIdx.x * 60 + (l + 1)) * 768;
#pragma unroll
            for (int i = 0; i < 3; i++) s.frag[768 + i * NTHR + tid] = src[i * NTHR + tid];
        }
        __syncthreads();
        // lat = h @ Wlat^T + blat
        for (int it = 0; it < 2; it++) {
            int idx = it * NTHR + tid, r = idx >> 4, j = idx & 15;
            float sum = s.blat[j];
#pragma unroll 8
            for (int k = 0; k < 192; k++) sum += s.h[r * 192 + k] * s.Wlat[j * 193 + k];
            s.lat[r * 17 + j] = sum;
            out_lat[((bbase + r) * 60 + l) * 16 + j] = sum;
        }
        __syncthreads();
        // out = (lat @ Wout^T + bout) / yscale_lev[l]
        if (tid < 160) {
            int r = tid / 5, n = tid % 5;
            float sum = s.bout[n];
#pragma unroll
            for (int j = 0; j < 16; j++) sum += s.lat[r * 17 + j] * s.Wout[n * 16 + j];
            out_lev[((bbase + r) * 60 + l) * 5 + n] = sum / yscale_lev[l * 5 + n];
        }
        // no extra barrier: next gemm reads frags (stable) and weights only
    }
    __syncthreads();
    // out_sfc = (h_last @ Wsfcout^T + bsfcout) / yscale_sca
    if (tid < 160) {
        int r = tid / 5, n = tid % 5;
        float sum = s.bsfco[n];
#pragma unroll 8
        for (int k = 0; k < 192; k++) sum += s.h[r * 192 + k] * s.Wsfco[n * 193 + k];
        out_sfc[(bbase + r) * 5 + n] = sum / s.ysca[n];
    }
}

extern "C" void kernel_launch(void* const* d_in, const int* in_sizes, int n_in,
                              void* d_out, int out_size) {
    (void)in_sizes; (void)n_in; (void)out_size;
    const float* x_lev     = (const float*)d_in[0];
    const float* x_sfc     = (const float*)d_in[1];
    const float* h_mem     = (const float*)d_in[2];
    const float* xmean_lev = (const float*)d_in[3];
    const float* xdiv_lev  = (const float*)d_in[4];
    const float* xmean_sca = (const float*)d_in[5];
    const float* xdiv_sca  = (const float*)d_in[6];
    const float* yscale_lev = (const float*)d_in[7];
    const float* yscale_sca = (const float*)d_in[8];
    const float* Wih1 = (const float*)d_in[9];
    const float* Whh1 = (const float*)d_in[10];
    const float* b1   = (const float*)d_in[11];
    const float* Wih2 = (const float*)d_in[12];
    const float* Whh2 = (const float*)d_in[13];
    const float* b2   = (const float*)d_in[14];
    const float* Wsfc1 = (const float*)d_in[15];
    const float* bsfc1 = (const float*)d_in[16];
    const float* Wsfc2 = (const float*)d_in[17];
    const float* bsfc2 = (const float*)d_in[18];
    const float* Wtoa1 = (const float*)d_in[19];
    const float* btoa1 = (const float*)d_in[20];
    const float* Wtoa2 = (const float*)d_in[21];
    const float* btoa2 = (const float*)d_in[22];
    const float* Wlat  = (const float*)d_in[23];
    const float* blat  = (const float*)d_in[24];
    const float* Wout  = (const float*)d_in[25];
    const float* bout  = (const float*)d_in[26];
    const float* Wsfcout = (const float*)d_in[27];
    const float* bsfcout = (const float*)d_in[28];

    cudaFuncSetAttribute(lstm_main, cudaFuncAttributeMaxDynamicSharedMemorySize,
                         (int)sizeof(Smem));

    int npack = 96 * KT2 * 32 + 96 * KT1 * 32;
    pack_kernel<<<(npack + 255) / 256, 256>>>(Wih1, Whh1, Wih2, Whh2);

    lstm_main<<<128, NTHR, sizeof(Smem)>>>(
        x_lev, x_sfc, h_mem, xmean_lev, xdiv_lev, xmean_sca, xdiv_sca,
        yscale_lev, yscale_sca, b1, b2,
        Wsfc1, bsfc1, Wsfc2, bsfc2, Wtoa1, btoa1, Wtoa2, btoa2,
        Wlat, blat, Wout, bout, Wsfcout, bsfcout,
        (float*)d_out);
}